// round 11
// baseline (speedup 1.0000x reference)
#include <cuda_runtime.h>
#include <cuda_bf16.h>
#include <math.h>
#include <stdint.h>

// Problem constants (fixed by the dataset)
#define M_ROWS   4096      // B*T
#define N_CAP    65536     // capacity
#define K_DIM    512       // d_mem
#define TOPK     64
#define NCAND    128       // candidate margin (provably safe vs bf16 GEMM error)
#define EQCAP    2048      // cap for threshold-bin candidate list

// ---------------------------------------------------------------------------
// Scratch (device globals — sanctioned scratch, no cudaMalloc)
// ---------------------------------------------------------------------------
__device__ __nv_bfloat16  g_scoresb[(size_t)M_ROWS * N_CAP];  // approx scores (bf16)
__device__ __nv_bfloat16  g_qb[(size_t)M_ROWS * K_DIM];       // bf16(query)
__device__ __nv_bfloat16  g_sb[(size_t)N_CAP * K_DIM];        // bf16(fp8 values) — EXACT
__device__ int            g_candidx[M_ROWS * NCAND];
__device__ int            g_topidx[M_ROWS * TOPK];
__device__ float          g_topval[M_ROWS * TOPK];            // exact scores of final 64

// ---------------------------------------------------------------------------
// Helpers (portable sm_80+ — compiles for both sm_103 and sm_103a passes)
// ---------------------------------------------------------------------------
__device__ __forceinline__ uint32_t smem_to_u32(const void* p) {
    uint32_t a;
    asm("{ .reg .u64 t; cvta.to.shared.u64 t, %1; cvt.u32.u64 %0, t; }" : "=r"(a) : "l"(p));
    return a;
}
__device__ __forceinline__ void cp_async16(uint32_t s, const void* g) {
    asm volatile("cp.async.cg.shared.global [%0], [%1], 16;" :: "r"(s), "l"(g) : "memory");
}
__device__ __forceinline__ void ldsm4(uint32_t* r, uint32_t a) {
    asm volatile("ldmatrix.sync.aligned.m8n8.x4.shared.b16 {%0,%1,%2,%3}, [%4];"
                 : "=r"(r[0]), "=r"(r[1]), "=r"(r[2]), "=r"(r[3]) : "r"(a));
}
__device__ __forceinline__ void mma16816(float* d, const uint32_t* a,
                                         uint32_t b0, uint32_t b1) {
    asm volatile("mma.sync.aligned.m16n8k16.row.col.f32.bf16.bf16.f32 "
                 "{%0,%1,%2,%3}, {%4,%5,%6,%7}, {%8,%9}, {%0,%1,%2,%3};"
                 : "+f"(d[0]), "+f"(d[1]), "+f"(d[2]), "+f"(d[3])
                 : "r"(a[0]), "r"(a[1]), "r"(a[2]), "r"(a[3]), "r"(b0), "r"(b1));
}
__device__ __forceinline__ unsigned f2key(float f) {
    unsigned u = __float_as_uint(f);
    return (u & 0x80000000u) ? ~u : (u | 0x80000000u);
}
// sortable 16-bit key for a raw bf16 pattern
__device__ __forceinline__ unsigned key16(unsigned h) {
    return (h & 0x8000u) ? (~h & 0xFFFFu) : (h | 0x8000u);
}
// warp-aggregated histogram add (defeats hot-bin atomic serialization)
__device__ __forceinline__ void hist_add(unsigned* hist, int bin) {
    unsigned m = __match_any_sync(0xFFFFFFFFu, bin);
    if ((threadIdx.x & 31) == (__ffs(m) - 1))
        atomicAdd(&hist[bin], (unsigned)__popc(m));
}

// ---------------------------------------------------------------------------
// Kernel 0: fp32 -> bf16 conversion of Q and storage (fp8 values exact in bf16)
// ---------------------------------------------------------------------------
__global__ __launch_bounds__(256)
void convert_kernel(const float* __restrict__ Q, const float* __restrict__ S)
{
    size_t i = (size_t)blockIdx.x * 256 + threadIdx.x;
    const size_t nS = (size_t)N_CAP * K_DIM / 4;
    const size_t nQ = (size_t)M_ROWS * K_DIM / 4;
    if (i < nS) {
        float4 v = ((const float4*)S)[i];
        __nv_bfloat162 a = __floats2bfloat162_rn(v.x, v.y);
        __nv_bfloat162 b = __floats2bfloat162_rn(v.z, v.w);
        uint2 o; o.x = *(uint32_t*)&a; o.y = *(uint32_t*)&b;
        ((uint2*)g_sb)[i] = o;
    }
    if (i < nQ) {
        float4 v = ((const float4*)Q)[i];
        __nv_bfloat162 a = __floats2bfloat162_rn(v.x, v.y);
        __nv_bfloat162 b = __floats2bfloat162_rn(v.z, v.w);
        uint2 o; o.x = *(uint32_t*)&a; o.y = *(uint32_t*)&b;
        ((uint2*)g_qb)[i] = o;
    }
}

// ---------------------------------------------------------------------------
// Kernel 1 (R7-proven config): bf16 mma.sync GEMM -> approx scores*scale -> bf16
// CTA tile 128x128, K-chunk 64, 3-stage cp.async pipeline, swizzled SMEM.
// 8 warps: warp grid 4(M) x 2(N), warp tile 32x64. 2 CTAs/SM.
// ---------------------------------------------------------------------------
#define GBM 128
#define GBN 128
#define NKC 8                       // 512/64 K-chunks
#define ATILE_B 16384               // 128 rows x 128 bytes
#define STAGE_B (2 * ATILE_B)       // A + B
#define DATA_OFF 512
#define GEMM_SMEM (DATA_OFF + 3 * STAGE_B)   // 98816

__global__ __launch_bounds__(256, 2)
void gemm_tc_kernel(const float* __restrict__ scale)
{
    extern __shared__ char smem[];
    float* sscale = (float*)smem;                 // 128 floats

    const int tid  = threadIdx.x;
    const int wid  = tid >> 5, lane = tid & 31;
    const int n0   = blockIdx.x * GBN;
    const int m0   = blockIdx.y * GBM;
    const int wm   = (wid >> 1) * 32;             // warp M offset
    const int wn   = (wid & 1) * 64;              // warp N offset

    for (int i = tid; i < GBN; i += 256) sscale[i] = scale[n0 + i];

    const uint32_t sbase = smem_to_u32(smem) + DATA_OFF;
    const char* qb = (const char*)g_qb;
    const char* kb = (const char*)g_sb;

    auto issue = [&](int kc) {
        const uint32_t sA = sbase + (kc % 3) * STAGE_B;
        const uint32_t sB = sA + ATILE_B;
        const size_t gk = (size_t)kc * 128;
#pragma unroll
        for (int it = 0; it < 4; it++) {
            int c = it * 256 + tid;                // 0..1023
            int row = c >> 3, seg = c & 7;
            uint32_t so = row * 128 + ((seg ^ (row & 7)) << 4);
            cp_async16(sA + so, qb + (size_t)(m0 + row) * 1024 + gk + seg * 16);
            cp_async16(sB + so, kb + (size_t)(n0 + row) * 1024 + gk + seg * 16);
        }
        asm volatile("cp.async.commit_group;" ::: "memory");
    };

    float acc[2][8][4];
#pragma unroll
    for (int mt = 0; mt < 2; mt++)
#pragma unroll
        for (int nt = 0; nt < 8; nt++)
#pragma unroll
            for (int e = 0; e < 4; e++) acc[mt][nt][e] = 0.0f;

    issue(0);
    issue(1);

    for (int kc = 0; kc < NKC; kc++) {
        if (kc + 2 < NKC) {
            issue(kc + 2);
            asm volatile("cp.async.wait_group 2;" ::: "memory");
        } else if (kc + 1 < NKC) {
            asm volatile("cp.async.wait_group 1;" ::: "memory");
        } else {
            asm volatile("cp.async.wait_group 0;" ::: "memory");
        }
        __syncthreads();

        const uint32_t sA = sbase + (kc % 3) * STAGE_B;
        const uint32_t sB = sA + ATILE_B;

#pragma unroll
        for (int k16 = 0; k16 < 4; k16++) {
            const int segk = k16 * 2 + (lane >> 4);
            uint32_t a[2][4];
#pragma unroll
            for (int mt = 0; mt < 2; mt++) {
                int row = wm + mt * 16 + (lane & 15);
                ldsm4(a[mt], sA + row * 128 + ((segk ^ (row & 7)) << 4));
            }
            uint32_t b[4][4];
#pragma unroll
            for (int nb = 0; nb < 4; nb++) {
                int row = wn + nb * 16 + (lane & 15);
                ldsm4(b[nb], sB + row * 128 + ((segk ^ (row & 7)) << 4));
            }
#pragma unroll
            for (int mt = 0; mt < 2; mt++)
#pragma unroll
                for (int nb = 0; nb < 4; nb++) {
                    mma16816(acc[mt][2 * nb],     a[mt], b[nb][0], b[nb][2]);
                    mma16816(acc[mt][2 * nb + 1], a[mt], b[nb][1], b[nb][3]);
                }
        }
        __syncthreads();
    }

    // epilogue: scale by column, pack to bf16 pairs
#pragma unroll
    for (int mt = 0; mt < 2; mt++) {
#pragma unroll
        for (int nt = 0; nt < 8; nt++) {
            int nl = wn + nt * 8 + (lane & 3) * 2;
            float s0 = sscale[nl], s1 = sscale[nl + 1];
            int mrow = m0 + wm + mt * 16 + (lane >> 2);
            size_t base = (size_t)mrow * N_CAP + n0 + nl;
            __nv_bfloat162 v0 = __floats2bfloat162_rn(acc[mt][nt][0] * s0, acc[mt][nt][1] * s1);
            __nv_bfloat162 v1 = __floats2bfloat162_rn(acc[mt][nt][2] * s0, acc[mt][nt][3] * s1);
            *(__nv_bfloat162*)&g_scoresb[base] = v0;
            *(__nv_bfloat162*)&g_scoresb[base + (size_t)8 * N_CAP] = v1;
        }
    }
}

// ---------------------------------------------------------------------------
// Kernel 2: per-row top-128 candidates on bf16 scores, two global passes:
//   A) 2048-bin histogram (top-11 key bits), uint4 streaming loads,
//      warp-aggregated atomics (hot exponent bins otherwise serialize)
//   B) uint4 collect of bins >= threshold; refine final 5 bits locally
// ---------------------------------------------------------------------------
__global__ __launch_bounds__(256)
void topk_kernel()
{
    const int r   = blockIdx.x;
    const int tid = threadIdx.x;
    const uint4* p4 = (const uint4*)&g_scoresb[(size_t)r << 16];   // 8192 uint4

    __shared__ unsigned hist[2048];
    __shared__ int binB, gHi_sh;
    __shared__ int eqLow[EQCAP];
    __shared__ int eqIdx[EQCAP];
    __shared__ int cntHi, cntEq;
    __shared__ unsigned h5[32];
    __shared__ int t5_sh, above5_sh, kkE_sh;

    for (int i = tid; i < 2048; i += 256) hist[i] = 0;
    if (tid == 0) { cntHi = 0; cntEq = 0; }
    __syncthreads();

    // Pass A: 8192 uint4 / 256 threads = 32 iters, 8 scores per load
    for (int i = tid; i < N_CAP / 8; i += 256) {
        uint4 u = __ldcs(&p4[i]);
        const uint32_t w[4] = { u.x, u.y, u.z, u.w };
#pragma unroll
        for (int j = 0; j < 4; j++) {
            hist_add(hist, (int)(key16(w[j] & 0xFFFFu) >> 5));
            hist_add(hist, (int)(key16(w[j] >> 16) >> 5));
        }
    }
    __syncthreads();

    if (tid == 0) {
        int acc = 0, b = 2047;
        for (; b >= 0; b--) {
            acc += (int)hist[b];
            if (acc >= NCAND) break;
        }
        binB = b;
        gHi_sh = acc - (int)hist[b];
    }
    __syncthreads();
    const int b = binB;

    // Pass B: collect
    for (int i = tid; i < N_CAP / 8; i += 256) {
        uint4 u = __ldcs(&p4[i]);
        const uint32_t w[4] = { u.x, u.y, u.z, u.w };
#pragma unroll
        for (int j = 0; j < 4; j++) {
#pragma unroll
            for (int h = 0; h < 2; h++) {
                unsigned k = key16(h == 0 ? (w[j] & 0xFFFFu) : (w[j] >> 16));
                int bin = (int)(k >> 5);
                if (bin > b) {
                    int pos = atomicAdd(&cntHi, 1);      // < NCAND guaranteed
                    g_candidx[r * NCAND + pos] = i * 8 + j * 2 + h;
                } else if (bin == b) {
                    int pos = atomicAdd(&cntEq, 1);
                    if (pos < EQCAP) {
                        eqLow[pos] = (int)(k & 31u);
                        eqIdx[pos] = i * 8 + j * 2 + h;
                    }
                }
            }
        }
    }
    if (tid < 32) h5[tid] = 0;
    __syncthreads();

    const int nEq = min(cntEq, EQCAP);
    for (int i = tid; i < nEq; i += 256) atomicAdd(&h5[eqLow[i]], 1u);
    __syncthreads();

    if (tid == 0) {
        int kk = NCAND - gHi_sh;
        int acc = 0, t = 31;
        for (; t >= 0; t--) {
            acc += (int)h5[t];
            if (acc >= kk) break;
        }
        t5_sh = t;
        above5_sh = acc - (int)h5[t];
        kkE_sh = kk - above5_sh;
        cntHi = gHi_sh;
        cntEq = 0;
    }
    __syncthreads();

    const int t5 = t5_sh, gHi = gHi_sh, above5 = above5_sh, kkE = kkE_sh;

    for (int i = tid; i < nEq; i += 256) {
        if (eqLow[i] > t5) {
            int pos = atomicAdd(&cntHi, 1);
            g_candidx[r * NCAND + pos] = eqIdx[i];
        }
    }
    __syncthreads();
    for (int i = tid; i < nEq; i += 256) {
        if (eqLow[i] == t5) {
            int p3 = atomicAdd(&cntEq, 1);
            if (p3 < kkE)
                g_candidx[r * NCAND + gHi + above5 + p3] = eqIdx[i];
        }
    }
}

// ---------------------------------------------------------------------------
// Kernel 3: exact rescore of 128 candidates + bitonic top-64.
// SMEM-staged coalesced gather in 128B chunks (17 KB staging -> ~2x occ of
// R10 variant), conflict-free readback, exact k-ascending FMA chain (R3).
// ---------------------------------------------------------------------------
#define RSTRIDE 33   // words per 32-word (128B) row chunk, +1 pad

__global__ __launch_bounds__(128)
void rescore_kernel(const float* __restrict__ Q, const float* __restrict__ scale)
{
    const int row = blockIdx.x;
    const int t   = threadIdx.x;

    __shared__ float    q[K_DIM];
    __shared__ int      idx[NCAND];
    __shared__ uint32_t sdata[NCAND * RSTRIDE];   // 16896 B

    for (int i = t; i < K_DIM; i += 128) q[i] = Q[(size_t)row * K_DIM + i];
    idx[t] = g_candidx[row * NCAND + t];
    __syncthreads();

    const float sc = scale[idx[t]];
    float acc = 0.0f;

#pragma unroll 1
    for (int chunk = 0; chunk < 8; chunk++) {
        // cooperative coalesced load: 128 rows x 8 uint4 segs = 1024 loads
#pragma unroll
        for (int it = 0; it < 8; it++) {
            int u = it * 128 + t;
            int j = u >> 3, seg = u & 7;
            uint4 v = *(const uint4*)((const char*)g_sb +
                        (size_t)idx[j] * 1024 + chunk * 128 + seg * 16);
            uint32_t* d = &sdata[j * RSTRIDE + seg * 4];
            d[0] = v.x; d[1] = v.y; d[2] = v.z; d[3] = v.w;
        }
        __syncthreads();

        // own-candidate accumulation, k-ascending (exact chain preserved)
        const uint32_t* myrow = &sdata[t * RSTRIDE];
        const float* qc = &q[chunk * 64];
#pragma unroll
        for (int w = 0; w < 32; w++) {
            __nv_bfloat162 b2 = *(const __nv_bfloat162*)&myrow[w];
            acc = fmaf(qc[2 * w],     __bfloat162float(b2.x) * sc, acc);
            acc = fmaf(qc[2 * w + 1], __bfloat162float(b2.y) * sc, acc);
        }
        __syncthreads();
    }

    __shared__ unsigned skey[NCAND];
    __shared__ float    sval[NCAND];
    __shared__ int      sidx[NCAND];
    skey[t] = f2key(acc); sval[t] = acc; sidx[t] = idx[t];
    __syncthreads();

    for (int ksz = 2; ksz <= NCAND; ksz <<= 1) {
        for (int j = ksz >> 1; j > 0; j >>= 1) {
            int ixj = t ^ j;
            if (ixj > t) {
                bool desc = ((t & ksz) == 0);
                unsigned ka = skey[t], kb = skey[ixj];
                bool sw = desc ? (ka < kb) : (ka > kb);
                if (sw) {
                    float va = sval[t]; int ia = sidx[t];
                    skey[t] = kb; sval[t] = sval[ixj]; sidx[t] = sidx[ixj];
                    skey[ixj] = ka; sval[ixj] = va; sidx[ixj] = ia;
                }
            }
            __syncthreads();
        }
    }

    if (t < TOPK) {
        g_topval[row * TOPK + t] = sval[t];
        g_topidx[row * TOPK + t] = sidx[t];
    }
}

// ---------------------------------------------------------------------------
// Kernel 4: softmax over exact top-64 + weighted dequantized gather (R3-proven)
// ---------------------------------------------------------------------------
__global__ __launch_bounds__(256)
void epilogue_kernel(const float* __restrict__ scale, float* __restrict__ out)
{
    const int r   = blockIdx.x;
    const int tid = threadIdx.x;

    __shared__ float w[TOPK];
    __shared__ float ssc[TOPK];
    __shared__ int   idx[TOPK];

    if (tid < TOPK) {
        w[tid]   = g_topval[r * TOPK + tid];
        int i    = g_topidx[r * TOPK + tid];
        idx[tid] = i;
        ssc[tid] = scale[i];
    }
    __syncthreads();

    if (tid == 0) {
        const float sqrtd = sqrtf((float)K_DIM);
        float li[TOPK];
        float mx = -1e30f;
        for (int k = 0; k < TOPK; k++) {
            li[k] = w[k] / sqrtd;
            mx = fmaxf(mx, li[k]);
        }
        float sum = 0.0f;
        for (int k = 0; k < TOPK; k++) {
            float e = expf(li[k] - mx);
            w[k] = e;
            sum += e;
        }
        for (int k = 0; k < TOPK; k++) w[k] = w[k] / sum;
    }
    __syncthreads();

    for (int d = tid; d < K_DIM; d += 256) {
        float acc = 0.0f;
#pragma unroll 8
        for (int k = 0; k < TOPK; k++) {
            float sel = __bfloat162float(g_sb[(size_t)idx[k] * K_DIM + d]) * ssc[k];
            acc = fmaf(w[k], sel, acc);
        }
        out[(size_t)r * K_DIM + d] = acc;
    }
}

// ---------------------------------------------------------------------------
// Launch
// ---------------------------------------------------------------------------
extern "C" void kernel_launch(void* const* d_in, const int* in_sizes, int n_in,
                              void* d_out, int out_size)
{
    const float* query = (const float*)d_in[0];   // (4,1024,512)
    const float* fp8s  = (const float*)d_in[1];   // (65536,512) fp8 values in fp32
    const float* scale = (const float*)d_in[2];   // (65536,1)
    float* out = (float*)d_out;

    cudaFuncSetAttribute(gemm_tc_kernel,
                         cudaFuncAttributeMaxDynamicSharedMemorySize, GEMM_SMEM);

    const int nS4 = N_CAP * K_DIM / 4;                     // 8388608
    convert_kernel<<<nS4 / 256, 256>>>(query, fp8s);

    dim3 gg(N_CAP / GBN, M_ROWS / GBM);                    // (512, 32)
    gemm_tc_kernel<<<gg, 256, GEMM_SMEM>>>(scale);

    topk_kernel<<<M_ROWS, 256>>>();

    rescore_kernel<<<M_ROWS, 128>>>(query, scale);

    epilogue_kernel<<<M_ROWS, 256>>>(scale, out);
}

// round 13
// speedup vs baseline: 1.5902x; 1.5902x over previous
#include <cuda_runtime.h>
#include <cuda_bf16.h>
#include <math.h>
#include <stdint.h>

// Problem constants (fixed by the dataset)
#define M_ROWS   4096      // B*T
#define N_CAP    65536     // capacity
#define K_DIM    512       // d_mem
#define TOPK     64
#define NCAND    128       // candidate margin (provably safe vs bf16 GEMM error)
#define EQCAP    2048      // cap for threshold-bin candidate list

// ---------------------------------------------------------------------------
// Scratch (device globals — sanctioned scratch, no cudaMalloc)
// ---------------------------------------------------------------------------
__device__ __nv_bfloat16  g_scoresb[(size_t)M_ROWS * N_CAP];  // approx scores (bf16)
__device__ __nv_bfloat16  g_qb[(size_t)M_ROWS * K_DIM];       // bf16(query)
__device__ __nv_bfloat16  g_sb[(size_t)N_CAP * K_DIM];        // bf16(fp8 values) — EXACT
__device__ int            g_candidx[M_ROWS * NCAND];
__device__ int            g_topidx[M_ROWS * TOPK];
__device__ float          g_topval[M_ROWS * TOPK];            // exact scores of final 64

// ---------------------------------------------------------------------------
// Helpers (portable sm_80+ — compiles for both sm_103 and sm_103a passes)
// ---------------------------------------------------------------------------
__device__ __forceinline__ uint32_t smem_to_u32(const void* p) {
    uint32_t a;
    asm("{ .reg .u64 t; cvta.to.shared.u64 t, %1; cvt.u32.u64 %0, t; }" : "=r"(a) : "l"(p));
    return a;
}
__device__ __forceinline__ void cp_async16(uint32_t s, const void* g) {
    asm volatile("cp.async.cg.shared.global [%0], [%1], 16;" :: "r"(s), "l"(g) : "memory");
}
__device__ __forceinline__ void ldsm4(uint32_t* r, uint32_t a) {
    asm volatile("ldmatrix.sync.aligned.m8n8.x4.shared.b16 {%0,%1,%2,%3}, [%4];"
                 : "=r"(r[0]), "=r"(r[1]), "=r"(r[2]), "=r"(r[3]) : "r"(a));
}
__device__ __forceinline__ void mma16816(float* d, const uint32_t* a,
                                         uint32_t b0, uint32_t b1) {
    asm volatile("mma.sync.aligned.m16n8k16.row.col.f32.bf16.bf16.f32 "
                 "{%0,%1,%2,%3}, {%4,%5,%6,%7}, {%8,%9}, {%0,%1,%2,%3};"
                 : "+f"(d[0]), "+f"(d[1]), "+f"(d[2]), "+f"(d[3])
                 : "r"(a[0]), "r"(a[1]), "r"(a[2]), "r"(a[3]), "r"(b0), "r"(b1));
}
__device__ __forceinline__ unsigned f2key(float f) {
    unsigned u = __float_as_uint(f);
    return (u & 0x80000000u) ? ~u : (u | 0x80000000u);
}
// sortable 16-bit key for a raw bf16 pattern
__device__ __forceinline__ unsigned key16(unsigned h) {
    return (h & 0x8000u) ? (~h & 0xFFFFu) : (h | 0x8000u);
}

// ---------------------------------------------------------------------------
// Kernel 0: fp32 -> bf16 conversion of Q and storage (fp8 values exact in bf16)
// ---------------------------------------------------------------------------
__global__ __launch_bounds__(256)
void convert_kernel(const float* __restrict__ Q, const float* __restrict__ S)
{
    size_t i = (size_t)blockIdx.x * 256 + threadIdx.x;
    const size_t nS = (size_t)N_CAP * K_DIM / 4;
    const size_t nQ = (size_t)M_ROWS * K_DIM / 4;
    if (i < nS) {
        float4 v = ((const float4*)S)[i];
        __nv_bfloat162 a = __floats2bfloat162_rn(v.x, v.y);
        __nv_bfloat162 b = __floats2bfloat162_rn(v.z, v.w);
        uint2 o; o.x = *(uint32_t*)&a; o.y = *(uint32_t*)&b;
        ((uint2*)g_sb)[i] = o;
    }
    if (i < nQ) {
        float4 v = ((const float4*)Q)[i];
        __nv_bfloat162 a = __floats2bfloat162_rn(v.x, v.y);
        __nv_bfloat162 b = __floats2bfloat162_rn(v.z, v.w);
        uint2 o; o.x = *(uint32_t*)&a; o.y = *(uint32_t*)&b;
        ((uint2*)g_qb)[i] = o;
    }
}

// ---------------------------------------------------------------------------
// Kernel 1 (R7-proven config): bf16 mma.sync GEMM -> approx scores*scale -> bf16
// CTA tile 128x128, K-chunk 64, 3-stage cp.async pipeline, swizzled SMEM.
// 8 warps: warp grid 4(M) x 2(N), warp tile 32x64. 2 CTAs/SM.
// ---------------------------------------------------------------------------
#define GBM 128
#define GBN 128
#define NKC 8                       // 512/64 K-chunks
#define ATILE_B 16384               // 128 rows x 128 bytes
#define STAGE_B (2 * ATILE_B)       // A + B
#define DATA_OFF 512
#define GEMM_SMEM (DATA_OFF + 3 * STAGE_B)   // 98816

__global__ __launch_bounds__(256, 2)
void gemm_tc_kernel(const float* __restrict__ scale)
{
    extern __shared__ char smem[];
    float* sscale = (float*)smem;                 // 128 floats

    const int tid  = threadIdx.x;
    const int wid  = tid >> 5, lane = tid & 31;
    const int n0   = blockIdx.x * GBN;
    const int m0   = blockIdx.y * GBM;
    const int wm   = (wid >> 1) * 32;             // warp M offset
    const int wn   = (wid & 1) * 64;              // warp N offset

    for (int i = tid; i < GBN; i += 256) sscale[i] = scale[n0 + i];

    const uint32_t sbase = smem_to_u32(smem) + DATA_OFF;
    const char* qb = (const char*)g_qb;
    const char* kb = (const char*)g_sb;

    auto issue = [&](int kc) {
        const uint32_t sA = sbase + (kc % 3) * STAGE_B;
        const uint32_t sB = sA + ATILE_B;
        const size_t gk = (size_t)kc * 128;
#pragma unroll
        for (int it = 0; it < 4; it++) {
            int c = it * 256 + tid;                // 0..1023
            int row = c >> 3, seg = c & 7;
            uint32_t so = row * 128 + ((seg ^ (row & 7)) << 4);
            cp_async16(sA + so, qb + (size_t)(m0 + row) * 1024 + gk + seg * 16);
            cp_async16(sB + so, kb + (size_t)(n0 + row) * 1024 + gk + seg * 16);
        }
        asm volatile("cp.async.commit_group;" ::: "memory");
    };

    float acc[2][8][4];
#pragma unroll
    for (int mt = 0; mt < 2; mt++)
#pragma unroll
        for (int nt = 0; nt < 8; nt++)
#pragma unroll
            for (int e = 0; e < 4; e++) acc[mt][nt][e] = 0.0f;

    issue(0);
    issue(1);

    for (int kc = 0; kc < NKC; kc++) {
        if (kc + 2 < NKC) {
            issue(kc + 2);
            asm volatile("cp.async.wait_group 2;" ::: "memory");
        } else if (kc + 1 < NKC) {
            asm volatile("cp.async.wait_group 1;" ::: "memory");
        } else {
            asm volatile("cp.async.wait_group 0;" ::: "memory");
        }
        __syncthreads();

        const uint32_t sA = sbase + (kc % 3) * STAGE_B;
        const uint32_t sB = sA + ATILE_B;

#pragma unroll
        for (int k16 = 0; k16 < 4; k16++) {
            const int segk = k16 * 2 + (lane >> 4);
            uint32_t a[2][4];
#pragma unroll
            for (int mt = 0; mt < 2; mt++) {
                int row = wm + mt * 16 + (lane & 15);
                ldsm4(a[mt], sA + row * 128 + ((segk ^ (row & 7)) << 4));
            }
            uint32_t b[4][4];
#pragma unroll
            for (int nb = 0; nb < 4; nb++) {
                int row = wn + nb * 16 + (lane & 15);
                ldsm4(b[nb], sB + row * 128 + ((segk ^ (row & 7)) << 4));
            }
#pragma unroll
            for (int mt = 0; mt < 2; mt++)
#pragma unroll
                for (int nb = 0; nb < 4; nb++) {
                    mma16816(acc[mt][2 * nb],     a[mt], b[nb][0], b[nb][2]);
                    mma16816(acc[mt][2 * nb + 1], a[mt], b[nb][1], b[nb][3]);
                }
        }
        __syncthreads();
    }

    // epilogue: scale by column, pack to bf16 pairs
#pragma unroll
    for (int mt = 0; mt < 2; mt++) {
#pragma unroll
        for (int nt = 0; nt < 8; nt++) {
            int nl = wn + nt * 8 + (lane & 3) * 2;
            float s0 = sscale[nl], s1 = sscale[nl + 1];
            int mrow = m0 + wm + mt * 16 + (lane >> 2);
            size_t base = (size_t)mrow * N_CAP + n0 + nl;
            __nv_bfloat162 v0 = __floats2bfloat162_rn(acc[mt][nt][0] * s0, acc[mt][nt][1] * s1);
            __nv_bfloat162 v1 = __floats2bfloat162_rn(acc[mt][nt][2] * s0, acc[mt][nt][3] * s1);
            *(__nv_bfloat162*)&g_scoresb[base] = v0;
            *(__nv_bfloat162*)&g_scoresb[base + (size_t)8 * N_CAP] = v1;
        }
    }
}

// ---------------------------------------------------------------------------
// Kernel 2 (R7/R10-proven): per-row top-128 candidates on bf16 scores,
// two global passes with cached scalar loads + plain shared atomics:
//   A) 2048-bin histogram of top-11 bits of the 16-bit sortable key
//   B) collect bins >= threshold bin; refine final 5 bits locally
// ---------------------------------------------------------------------------
__global__ __launch_bounds__(256)
void topk_kernel()
{
    const int r   = blockIdx.x;
    const int tid = threadIdx.x;
    const uint32_t* p = (const uint32_t*)&g_scoresb[(size_t)r << 16];   // 32768 pairs

    __shared__ unsigned hist[2048];
    __shared__ int binB, gHi_sh;
    __shared__ int eqLow[EQCAP];
    __shared__ int eqIdx[EQCAP];
    __shared__ int cntHi, cntEq;
    __shared__ unsigned h5[32];
    __shared__ int t5_sh, above5_sh, kkE_sh;

    for (int i = tid; i < 2048; i += 256) hist[i] = 0;
    if (tid == 0) { cntHi = 0; cntEq = 0; }
    __syncthreads();

    for (int i = tid; i < N_CAP / 2; i += 256) {
        uint32_t u = p[i];
        atomicAdd(&hist[key16(u & 0xFFFFu) >> 5], 1u);
        atomicAdd(&hist[key16(u >> 16) >> 5], 1u);
    }
    __syncthreads();

    if (tid == 0) {
        int acc = 0, b = 2047;
        for (; b >= 0; b--) {
            acc += (int)hist[b];
            if (acc >= NCAND) break;
        }
        binB = b;
        gHi_sh = acc - (int)hist[b];
    }
    __syncthreads();
    const int b = binB;

    for (int i = tid; i < N_CAP / 2; i += 256) {
        uint32_t u = p[i];
#pragma unroll
        for (int h = 0; h < 2; h++) {
            unsigned k = key16(h == 0 ? (u & 0xFFFFu) : (u >> 16));
            int bin = (int)(k >> 5);
            if (bin > b) {
                int pos = atomicAdd(&cntHi, 1);      // < NCAND guaranteed
                g_candidx[r * NCAND + pos] = 2 * i + h;
            } else if (bin == b) {
                int pos = atomicAdd(&cntEq, 1);
                if (pos < EQCAP) {
                    eqLow[pos] = (int)(k & 31u);
                    eqIdx[pos] = 2 * i + h;
                }
            }
        }
    }
    if (tid < 32) h5[tid] = 0;
    __syncthreads();

    const int nEq = min(cntEq, EQCAP);
    for (int i = tid; i < nEq; i += 256) atomicAdd(&h5[eqLow[i]], 1u);
    __syncthreads();

    if (tid == 0) {
        int kk = NCAND - gHi_sh;
        int acc = 0, t = 31;
        for (; t >= 0; t--) {
            acc += (int)h5[t];
            if (acc >= kk) break;
        }
        t5_sh = t;
        above5_sh = acc - (int)h5[t];
        kkE_sh = kk - above5_sh;
        cntHi = gHi_sh;
        cntEq = 0;
    }
    __syncthreads();

    const int t5 = t5_sh, gHi = gHi_sh, above5 = above5_sh, kkE = kkE_sh;

    for (int i = tid; i < nEq; i += 256) {
        if (eqLow[i] > t5) {
            int pos = atomicAdd(&cntHi, 1);
            g_candidx[r * NCAND + pos] = eqIdx[i];
        }
    }
    __syncthreads();
    for (int i = tid; i < nEq; i += 256) {
        if (eqLow[i] == t5) {
            int p3 = atomicAdd(&cntEq, 1);
            if (p3 < kkE)
                g_candidx[r * NCAND + gHi + above5 + p3] = eqIdx[i];
        }
    }
}

// ---------------------------------------------------------------------------
// Kernel 3 (R11-proven): exact rescore of 128 candidates + bitonic top-64.
// SMEM-staged coalesced gather in 128B chunks, conflict-free readback,
// exact k-ascending FMA chain (R3).
// ---------------------------------------------------------------------------
#define RSTRIDE 33   // words per 32-word (128B) row chunk, +1 pad

__global__ __launch_bounds__(128)
void rescore_kernel(const float* __restrict__ Q, const float* __restrict__ scale)
{
    const int row = blockIdx.x;
    const int t   = threadIdx.x;

    __shared__ float    q[K_DIM];
    __shared__ int      idx[NCAND];
    __shared__ uint32_t sdata[NCAND * RSTRIDE];   // 16896 B

    for (int i = t; i < K_DIM; i += 128) q[i] = Q[(size_t)row * K_DIM + i];
    idx[t] = g_candidx[row * NCAND + t];
    __syncthreads();

    const float sc = scale[idx[t]];
    float acc = 0.0f;

#pragma unroll 1
    for (int chunk = 0; chunk < 8; chunk++) {
        // cooperative coalesced load: 128 rows x 8 uint4 segs = 1024 loads
#pragma unroll
        for (int it = 0; it < 8; it++) {
            int u = it * 128 + t;
            int j = u >> 3, seg = u & 7;
            uint4 v = *(const uint4*)((const char*)g_sb +
                        (size_t)idx[j] * 1024 + chunk * 128 + seg * 16);
            uint32_t* d = &sdata[j * RSTRIDE + seg * 4];
            d[0] = v.x; d[1] = v.y; d[2] = v.z; d[3] = v.w;
        }
        __syncthreads();

        // own-candidate accumulation, k-ascending (exact chain preserved)
        const uint32_t* myrow = &sdata[t * RSTRIDE];
        const float* qc = &q[chunk * 64];
#pragma unroll
        for (int w = 0; w < 32; w++) {
            __nv_bfloat162 b2 = *(const __nv_bfloat162*)&myrow[w];
            acc = fmaf(qc[2 * w],     __bfloat162float(b2.x) * sc, acc);
            acc = fmaf(qc[2 * w + 1], __bfloat162float(b2.y) * sc, acc);
        }
        __syncthreads();
    }

    __shared__ unsigned skey[NCAND];
    __shared__ float    sval[NCAND];
    __shared__ int      sidx[NCAND];
    skey[t] = f2key(acc); sval[t] = acc; sidx[t] = idx[t];
    __syncthreads();

    for (int ksz = 2; ksz <= NCAND; ksz <<= 1) {
        for (int j = ksz >> 1; j > 0; j >>= 1) {
            int ixj = t ^ j;
            if (ixj > t) {
                bool desc = ((t & ksz) == 0);
                unsigned ka = skey[t], kb = skey[ixj];
                bool sw = desc ? (ka < kb) : (ka > kb);
                if (sw) {
                    float va = sval[t]; int ia = sidx[t];
                    skey[t] = kb; sval[t] = sval[ixj]; sidx[t] = sidx[ixj];
                    skey[ixj] = ka; sval[ixj] = va; sidx[ixj] = ia;
                }
            }
            __syncthreads();
        }
    }

    if (t < TOPK) {
        g_topval[row * TOPK + t] = sval[t];
        g_topidx[row * TOPK + t] = sidx[t];
    }
}

// ---------------------------------------------------------------------------
// Kernel 4: softmax over exact top-64 + weighted dequantized gather (R3-proven)
// ---------------------------------------------------------------------------
__global__ __launch_bounds__(256)
void epilogue_kernel(const float* __restrict__ scale, float* __restrict__ out)
{
    const int r   = blockIdx.x;
    const int tid = threadIdx.x;

    __shared__ float w[TOPK];
    __shared__ float ssc[TOPK];
    __shared__ int   idx[TOPK];

    if (tid < TOPK) {
        w[tid]   = g_topval[r * TOPK + tid];
        int i    = g_topidx[r * TOPK + tid];
        idx[tid] = i;
        ssc[tid] = scale[i];
    }
    __syncthreads();

    if (tid == 0) {
        const float sqrtd = sqrtf((float)K_DIM);
        float li[TOPK];
        float mx = -1e30f;
        for (int k = 0; k < TOPK; k++) {
            li[k] = w[k] / sqrtd;
            mx = fmaxf(mx, li[k]);
        }
        float sum = 0.0f;
        for (int k = 0; k < TOPK; k++) {
            float e = expf(li[k] - mx);
            w[k] = e;
            sum += e;
        }
        for (int k = 0; k < TOPK; k++) w[k] = w[k] / sum;
    }
    __syncthreads();

    for (int d = tid; d < K_DIM; d += 256) {
        float acc = 0.0f;
#pragma unroll 8
        for (int k = 0; k < TOPK; k++) {
            float sel = __bfloat162float(g_sb[(size_t)idx[k] * K_DIM + d]) * ssc[k];
            acc = fmaf(w[k], sel, acc);
        }
        out[(size_t)r * K_DIM + d] = acc;
    }
}

// ---------------------------------------------------------------------------
// Launch
// ---------------------------------------------------------------------------
extern "C" void kernel_launch(void* const* d_in, const int* in_sizes, int n_in,
                              void* d_out, int out_size)
{
    const float* query = (const float*)d_in[0];   // (4,1024,512)
    const float* fp8s  = (const float*)d_in[1];   // (65536,512) fp8 values in fp32
    const float* scale = (const float*)d_in[2];   // (65536,1)
    float* out = (float*)d_out;

    cudaFuncSetAttribute(gemm_tc_kernel,
                         cudaFuncAttributeMaxDynamicSharedMemorySize, GEMM_SMEM);

    const int nS4 = N_CAP * K_DIM / 4;                     // 8388608
    convert_kernel<<<nS4 / 256, 256>>>(query, fp8s);

    dim3 gg(N_CAP / GBN, M_ROWS / GBM);                    // (512, 32)
    gemm_tc_kernel<<<gg, 256, GEMM_SMEM>>>(scale);

    topk_kernel<<<M_ROWS, 256>>>();

    rescore_kernel<<<M_ROWS, 128>>>(query, scale);

    epilogue_kernel<<<M_ROWS, 256>>>(scale, out);
}